// round 1
// baseline (speedup 1.0000x reference)
#include <cuda_runtime.h>
#include <math.h>

#define BB   8
#define SS   4096
#define DIMM 1024
#define HH   16
#define HDD  64
#define BSR  (BB * SS)          /* 32768 rows */
#define QKVN (3 * DIMM)         /* 3072 */
#define TSPLIT 32
#define SCALE_F 0.125f          /* 64^-0.5 */

/* -------- scratch (device globals: allocation-free rule) -------- */
__device__ float g_qkv[(size_t)BSR * QKVN];                       /* 402 MB */
__device__ float g_attn[(size_t)BSR * DIMM];                      /* 134 MB */
__device__ float g_Apart[(size_t)TSPLIT * BB * HH * HDD * HDD];   /* 67 MB  */
__device__ float g_A[(size_t)BB * HH * HDD * HDD];                /* 2 MB   */

/* ---------------------------------------------------------------
 * SGEMM: C[M,N] = A[M,K] @ B[K,N] + bias[N]
 * 128x128 block tile, BK=16, 256 threads, 8x8 per thread (4+4 raked),
 * global->reg prefetch, As stored transposed with pad.
 * M%128==0, N%128==0, K%16==0 guaranteed by problem shapes.
 * --------------------------------------------------------------- */
__global__ void __launch_bounds__(256, 2)
sgemm_bias(const float* __restrict__ A, const float* __restrict__ B,
           const float* __restrict__ bias, float* __restrict__ C,
           int M, int N, int K)
{
    __shared__ __align__(16) float As[16][132];
    __shared__ __align__(16) float Bs[16][128];

    const int tid  = threadIdx.x;
    const int tcol = tid & 15;     /* n sub-tile */
    const int trow = tid >> 4;     /* m sub-tile */

    const int a_row = tid >> 2;    /* 0..63  */
    const int a_c4  = tid & 3;     /* 0..3   */
    const int b_row = tid >> 5;    /* 0..7   */
    const int b_c4  = tid & 31;    /* 0..31  */

    const float* Ab = A + (size_t)blockIdx.y * 128 * K;
    const float* Bb = B + (size_t)blockIdx.x * 128;

    float acc[8][8];
#pragma unroll
    for (int i = 0; i < 8; i++)
#pragma unroll
        for (int j = 0; j < 8; j++) acc[i][j] = 0.f;

    /* prefetch first k-tile */
    float4 pa0 = *(const float4*)(Ab + (size_t)a_row * K + a_c4 * 4);
    float4 pa1 = *(const float4*)(Ab + (size_t)(a_row + 64) * K + a_c4 * 4);
    float4 pb0 = *(const float4*)(Bb + (size_t)b_row * N + b_c4 * 4);
    float4 pb1 = *(const float4*)(Bb + (size_t)(b_row + 8) * N + b_c4 * 4);

    for (int k0 = 0; k0 < K; k0 += 16) {
        /* commit prefetched tile to smem */
        As[a_c4 * 4 + 0][a_row]      = pa0.x;
        As[a_c4 * 4 + 1][a_row]      = pa0.y;
        As[a_c4 * 4 + 2][a_row]      = pa0.z;
        As[a_c4 * 4 + 3][a_row]      = pa0.w;
        As[a_c4 * 4 + 0][a_row + 64] = pa1.x;
        As[a_c4 * 4 + 1][a_row + 64] = pa1.y;
        As[a_c4 * 4 + 2][a_row + 64] = pa1.z;
        As[a_c4 * 4 + 3][a_row + 64] = pa1.w;
        *(float4*)&Bs[b_row][b_c4 * 4]     = pb0;
        *(float4*)&Bs[b_row + 8][b_c4 * 4] = pb1;
        __syncthreads();

        /* prefetch next tile (clamped to a valid address; unused on last iter) */
        int kn = (k0 + 16 < K) ? (k0 + 16) : 0;
        pa0 = *(const float4*)(Ab + (size_t)a_row * K + kn + a_c4 * 4);
        pa1 = *(const float4*)(Ab + (size_t)(a_row + 64) * K + kn + a_c4 * 4);
        pb0 = *(const float4*)(Bb + (size_t)(kn + b_row) * N + b_c4 * 4);
        pb1 = *(const float4*)(Bb + (size_t)(kn + b_row + 8) * N + b_c4 * 4);

#pragma unroll
        for (int kk = 0; kk < 16; kk++) {
            float ar[8], br[8];
            *(float4*)&ar[0] = *(const float4*)&As[kk][trow * 4];
            *(float4*)&ar[4] = *(const float4*)&As[kk][64 + trow * 4];
            *(float4*)&br[0] = *(const float4*)&Bs[kk][tcol * 4];
            *(float4*)&br[4] = *(const float4*)&Bs[kk][64 + tcol * 4];
#pragma unroll
            for (int i = 0; i < 8; i++)
#pragma unroll
                for (int j = 0; j < 8; j++)
                    acc[i][j] += ar[i] * br[j];
        }
        __syncthreads();
    }

    /* epilogue: + bias, write float4s */
    const int cb = blockIdx.x * 128;
    float bia[8];
    *(float4*)&bia[0] = *(const float4*)(bias + cb + tcol * 4);
    *(float4*)&bia[4] = *(const float4*)(bias + cb + 64 + tcol * 4);
#pragma unroll
    for (int i = 0; i < 8; i++) {
        int r = blockIdx.y * 128 + ((i < 4) ? (trow * 4 + i) : (64 + trow * 4 + i - 4));
        float* Crow = C + (size_t)r * N + cb;
        float4 v0 = make_float4(acc[i][0] + bia[0], acc[i][1] + bia[1],
                                acc[i][2] + bia[2], acc[i][3] + bia[3]);
        float4 v1 = make_float4(acc[i][4] + bia[4], acc[i][5] + bia[5],
                                acc[i][6] + bia[6], acc[i][7] + bia[7]);
        *(float4*)(Crow + tcol * 4)      = v0;
        *(float4*)(Crow + 64 + tcol * 4) = v1;
    }
}

/* ---------------------------------------------------------------
 * Q softmax over seqlen (axis s), in place, folds in SCALE.
 * Column = (b, h*64+d), stride between s rows = 3072 floats.
 * Block = 32 cols x 8 row-lanes (coalesced across cols).
 * grid: BB * (DIMM/32)
 * --------------------------------------------------------------- */
__global__ void q_softmax_kernel(float* __restrict__ qkv)
{
    const int b       = blockIdx.x / (DIMM / 32);
    const int colbase = (blockIdx.x % (DIMM / 32)) * 32;
    const int c = threadIdx.x & 31;
    const int r = threadIdx.x >> 5;   /* 0..7 */
    const int stride = QKVN;
    float* base = qkv + (size_t)b * SS * stride + colbase + c;

    __shared__ float red[8][32];

    float mx = -INFINITY;
    for (int s = r; s < SS; s += 8)
        mx = fmaxf(mx, base[(size_t)s * stride]);
    red[r][c] = mx;
    __syncthreads();
    if (r == 0) {
        float m = red[0][c];
#pragma unroll
        for (int i = 1; i < 8; i++) m = fmaxf(m, red[i][c]);
        red[0][c] = m;
    }
    __syncthreads();
    mx = red[0][c];
    __syncthreads();

    float sum = 0.f;
    for (int s = r; s < SS; s += 8)
        sum += expf(base[(size_t)s * stride] - mx);
    red[r][c] = sum;
    __syncthreads();
    if (r == 0) {
        float t = 0.f;
#pragma unroll
        for (int i = 0; i < 8; i++) t += red[i][c];
        red[0][c] = t;
    }
    __syncthreads();
    const float inv = SCALE_F / red[0][c];

    for (int s = r; s < SS; s += 8) {
        size_t off = (size_t)s * stride;
        base[off] = expf(base[off] - mx) * inv;
    }
}

/* ---------------------------------------------------------------
 * K softmax over head_dim (64 contiguous floats), in place.
 * One warp per (b,s,h) row; grid = BSR*HH/8, block 256 (8 warps).
 * --------------------------------------------------------------- */
__global__ void k_softmax_kernel(float* __restrict__ qkv)
{
    const int row  = blockIdx.x * 8 + (threadIdx.x >> 5); /* (b*s)*H + h */
    const int lane = threadIdx.x & 31;
    float* p = qkv + (size_t)(row / HH) * QKVN + DIMM + (row % HH) * HDD;

    float v0 = p[lane], v1 = p[lane + 32];
    float m = fmaxf(v0, v1);
#pragma unroll
    for (int o = 16; o > 0; o >>= 1)
        m = fmaxf(m, __shfl_xor_sync(0xFFFFFFFFu, m, o));
    float e0 = expf(v0 - m), e1 = expf(v1 - m);
    float s = e0 + e1;
#pragma unroll
    for (int o = 16; o > 0; o >>= 1)
        s += __shfl_xor_sync(0xFFFFFFFFu, s, o);
    float inv = 1.f / s;
    p[lane]      = e0 * inv;
    p[lane + 32] = e1 * inv;
}

/* ---------------------------------------------------------------
 * A_part[ts, b, h, d, e] = sum over a 128-long t-slice of k[t,d]*q[t,e]
 * grid: BB*HH*TSPLIT, block 256 (each thread a 4x4 of the 64x64 tile)
 * --------------------------------------------------------------- */
__global__ void ktq_kernel(const float* __restrict__ qkv, float* __restrict__ Apart)
{
    const int bh = blockIdx.x / TSPLIT;
    const int ts = blockIdx.x % TSPLIT;
    const int b = bh / HH, h = bh % HH;
    const int TCHUNK = SS / TSPLIT;   /* 128 */

    __shared__ __align__(16) float ks[32][64];
    __shared__ __align__(16) float qs[32][64];

    const int tid = threadIdx.x;
    const int tc = tid & 15;   /* e */
    const int tr = tid >> 4;   /* d */
    const int lr = tid >> 3;   /* 0..31 load row */
    const int lc = tid & 7;    /* 0..7 float4 col */

    float acc[4][4];
#pragma unroll
    for (int i = 0; i < 4; i++)
#pragma unroll
        for (int j = 0; j < 4; j++) acc[i][j] = 0.f;

    const float* base = qkv + ((size_t)b * SS + (size_t)ts * TCHUNK) * QKVN;

    for (int t0 = 0; t0 < TCHUNK; t0 += 32) {
        const float* qrow = base + (size_t)(t0 + lr) * QKVN + h * HDD;  /* q at off 0 */
        const float* krow = qrow + DIMM;                                 /* k at off DIM */
        *(float4*)&qs[lr][lc * 4]      = *(const float4*)(qrow + lc * 4);
        *(float4*)&qs[lr][lc * 4 + 32] = *(const float4*)(qrow + lc * 4 + 32);
        *(float4*)&ks[lr][lc * 4]      = *(const float4*)(krow + lc * 4);
        *(float4*)&ks[lr][lc * 4 + 32] = *(const float4*)(krow + lc * 4 + 32);
        __syncthreads();
#pragma unroll
        for (int kk = 0; kk < 32; kk++) {
            float kr[4], qr[4];
            *(float4*)kr = *(const float4*)&ks[kk][tr * 4];
            *(float4*)qr = *(const float4*)&qs[kk][tc * 4];
#pragma unroll
            for (int i = 0; i < 4; i++)
#pragma unroll
                for (int j = 0; j < 4; j++)
                    acc[i][j] += kr[i] * qr[j];
        }
        __syncthreads();
    }

    float* outp = Apart + ((size_t)ts * BB * HH + bh) * HDD * HDD;
#pragma unroll
    for (int i = 0; i < 4; i++) {
        float4 v = make_float4(acc[i][0], acc[i][1], acc[i][2], acc[i][3]);
        *(float4*)&outp[(tr * 4 + i) * HDD + tc * 4] = v;
    }
}

/* reduce TSPLIT partials -> g_A; grid = B*H*64*64/256 */
__global__ void a_reduce_kernel(const float* __restrict__ Apart, float* __restrict__ A)
{
    const int idx = blockIdx.x * 256 + threadIdx.x;
    const size_t stride = (size_t)BB * HH * HDD * HDD;
    float s = 0.f;
#pragma unroll
    for (int p = 0; p < TSPLIT; p++)
        s += Apart[(size_t)p * stride + idx];
    A[idx] = s;
}

/* ---------------------------------------------------------------
 * attn[b, s, h*64+e] = sum_d v[b,s,h,d] * A[b,h,d,e]
 * grid: BB*HH*(SS/64), block 256 (each thread 4 s-rows x 4 e-cols)
 * --------------------------------------------------------------- */
__global__ void vA_kernel(const float* __restrict__ qkv, const float* __restrict__ Amat,
                          float* __restrict__ outp)
{
    const int stile = blockIdx.x % (SS / 64);
    const int bh    = blockIdx.x / (SS / 64);
    const int b = bh / HH, h = bh % HH;

    __shared__ __align__(16) float Am[64][64];
    __shared__ __align__(16) float vs[64][68];

    const int tid = threadIdx.x;
    const int tc = tid & 15;   /* e */
    const int tr = tid >> 4;   /* s */

    /* load A (64x64) flat: 1024 float4 / 256 threads = 4 */
    {
        const float4* Ab = (const float4*)(Amat + (size_t)bh * HDD * HDD);
        float4* Ad = (float4*)&Am[0][0];
#pragma unroll
        for (int i = 0; i < 4; i++) Ad[tid + i * 256] = Ab[tid + i * 256];
    }
    /* load v tile (64 rows x 64 floats) */
    {
        const int lr = tid >> 2;   /* 0..63 */
        const int lc = tid & 3;    /* 0..3  */
        const float* vrow = qkv + ((size_t)b * SS + (size_t)stile * 64 + lr) * QKVN
                            + 2 * DIMM + h * HDD;
#pragma unroll
        for (int m = 0; m < 4; m++)
            *(float4*)&vs[lr][(lc + 4 * m) * 4] = *(const float4*)(vrow + (lc + 4 * m) * 4);
    }
    __syncthreads();

    float acc[4][4];
#pragma unroll
    for (int i = 0; i < 4; i++)
#pragma unroll
        for (int j = 0; j < 4; j++) acc[i][j] = 0.f;

#pragma unroll 8
    for (int d = 0; d < 64; d++) {
        float br[4];
        *(float4*)br = *(const float4*)&Am[d][tc * 4];
        float vr[4];
#pragma unroll
        for (int i = 0; i < 4; i++) vr[i] = vs[tr * 4 + i][d];
#pragma unroll
        for (int i = 0; i < 4; i++)
#pragma unroll
            for (int j = 0; j < 4; j++)
                acc[i][j] += vr[i] * br[j];
    }

#pragma unroll
    for (int i = 0; i < 4; i++) {
        size_t row = (size_t)b * SS + (size_t)stile * 64 + tr * 4 + i;
        float4 v = make_float4(acc[i][0], acc[i][1], acc[i][2], acc[i][3]);
        *(float4*)(outp + row * DIMM + h * HDD + tc * 4) = v;
    }
}

/* --------------------------------------------------------------- */
extern "C" void kernel_launch(void* const* d_in, const int* in_sizes, int n_in,
                              void* d_out, int out_size)
{
    (void)in_sizes; (void)n_in; (void)out_size;
    const float* x     = (const float*)d_in[0];
    const float* Wqkv  = (const float*)d_in[1];
    const float* bqkv  = (const float*)d_in[2];
    const float* Wproj = (const float*)d_in[3];
    const float* bproj = (const float*)d_in[4];
    float* out = (float*)d_out;

    float *qkv, *attn, *Apart, *Amat;
    cudaGetSymbolAddress((void**)&qkv,   g_qkv);
    cudaGetSymbolAddress((void**)&attn,  g_attn);
    cudaGetSymbolAddress((void**)&Apart, g_Apart);
    cudaGetSymbolAddress((void**)&Amat,  g_A);

    /* 1) qkv = x @ Wqkv + bqkv   [32768 x 3072] */
    {
        dim3 grid(QKVN / 128, BSR / 128);
        sgemm_bias<<<grid, 256>>>(x, Wqkv, bqkv, qkv, BSR, QKVN, DIMM);
    }
    /* 2) softmaxes (in place in qkv) */
    q_softmax_kernel<<<BB * (DIMM / 32), 256>>>(qkv);
    k_softmax_kernel<<<(BSR * HH) / 8, 256>>>(qkv);
    /* 3) A = K^T Q per (b,h), t-split partials + reduce */
    ktq_kernel<<<BB * HH * TSPLIT, 256>>>(qkv, Apart);
    a_reduce_kernel<<<(BB * HH * HDD * HDD) / 256, 256>>>(Apart, Amat);
    /* 4) attn = V @ A per (b,h) */
    vA_kernel<<<BB * HH * (SS / 64), 256>>>(qkv, Amat, attn);
    /* 5) out = attn @ Wproj + bproj   [32768 x 1024] */
    {
        dim3 grid(DIMM / 128, BSR / 128);
        sgemm_bias<<<grid, 256>>>(attn, Wproj, bproj, out, BSR, DIMM, DIMM);
    }
}

// round 3
// speedup vs baseline: 1.7675x; 1.7675x over previous
#include <cuda_runtime.h>
#include <cstdint>
#include <math.h>

#define BB   8
#define SS   4096
#define DIMM 1024
#define HH   16
#define HDD  64
#define BSR  (BB * SS)          /* 32768 rows */
#define QKVN (3 * DIMM)         /* 3072 */
#define TSPLIT 32
#define SCALE_F 0.125f          /* 64^-0.5 */
#define KDIM 1024               /* K of both big GEMMs */

/* -------- scratch (device globals: allocation-free rule) -------- */
__device__ float g_qkv[(size_t)BSR * QKVN];                       /* 402 MB */
__device__ float g_attn[(size_t)BSR * DIMM];                      /* 134 MB */
__device__ float g_Apart[(size_t)TSPLIT * BB * HH * HDD * HDD];   /* 67 MB  */
__device__ float g_A[(size_t)BB * HH * HDD * HDD];                /* 2 MB   */
__device__ float g_WqkvT[(size_t)QKVN * DIMM];                    /* 12 MB  */
__device__ float g_WprojT[(size_t)DIMM * DIMM];                   /* 4 MB   */

/* ================= tf32 mma.sync GEMM =================
 * C[M,N] = A[M,1024] @ BT[N,1024]^T + bias
 * Tile 128x128, BK=32, 256 threads (8 warps 2x4), warp tile 64x32,
 * mma.sync.m16n8k8.tf32, 2-stage cp.async pipeline.
 * Smem layout: [row][36] (pad 4) -> conflict-free fragment LDS. */

#define BKK   32
#define ASTR  36                      /* padded row stride in floats */
#define STG_F (128 * ASTR)            /* floats per stage per matrix */
#define SMEM_DYN_G (4 * STG_F * 4)    /* 2 stages x (A+B) = 73728 B */
#define NCH   (KDIM / BKK)            /* 32 */

__device__ __forceinline__ uint32_t smem_u32(const void* p) {
    uint32_t a;
    asm("{ .reg .u64 t; cvta.to.shared.u64 t, %1; cvt.u32.u64 %0, t; }"
        : "=r"(a) : "l"(p));
    return a;
}
__device__ __forceinline__ void cp16(uint32_t dst, const void* src) {
    asm volatile("cp.async.cg.shared.global [%0], [%1], 16;"
                 :: "r"(dst), "l"(src) : "memory");
}
__device__ __forceinline__ uint32_t f2tf32(float x) {
    uint32_t r;
    asm("cvt.rna.tf32.f32 %0, %1;" : "=r"(r) : "f"(x));
    return r;
}
__device__ __forceinline__ void mma_tf32(float* c, const uint32_t* a, const uint32_t* b) {
    asm volatile("mma.sync.aligned.m16n8k8.row.col.f32.tf32.tf32.f32 "
                 "{%0,%1,%2,%3}, {%4,%5,%6,%7}, {%8,%9}, {%0,%1,%2,%3};"
                 : "+f"(c[0]), "+f"(c[1]), "+f"(c[2]), "+f"(c[3])
                 : "r"(a[0]), "r"(a[1]), "r"(a[2]), "r"(a[3]),
                   "r"(b[0]), "r"(b[1]));
}

__global__ void __launch_bounds__(256, 2)
gemm_tc(const float* __restrict__ A, const float* __restrict__ BT,
        const float* __restrict__ bias, float* __restrict__ C, int N)
{
    extern __shared__ __align__(16) float sm[];
    float* Bsm = sm + 2 * STG_F;
    const uint32_t uA = smem_u32(sm);
    const uint32_t uB = uA + 2 * STG_F * 4;

    const int tid  = threadIdx.x;
    const int lane = tid & 31;
    const int warp = tid >> 5;
    const int wm   = warp & 1;          /* warp row: 0..1 */
    const int wn   = warp >> 1;         /* warp col: 0..3 */
    const int g    = lane >> 2;         /* group 0..7 */
    const int tig  = lane & 3;          /* 0..3 */

    /* global load mapping: 2 threads per row, 16 floats each */
    const int arow = tid >> 1;          /* 0..127 */
    const int seg  = (tid & 1) * 16;    /* float offset in row */
    const float* Ag = A  + (size_t)(blockIdx.y * 128 + arow) * KDIM + seg;
    const float* Bg = BT + (size_t)(blockIdx.x * 128 + arow) * KDIM + seg;
    const uint32_t dstA = uA + (uint32_t)(arow * ASTR + seg) * 4;
    const uint32_t dstB = uB + (uint32_t)(arow * ASTR + seg) * 4;

    float acc[4][4][4];
#pragma unroll
    for (int i = 0; i < 4; i++)
#pragma unroll
        for (int j = 0; j < 4; j++)
#pragma unroll
            for (int r = 0; r < 4; r++) acc[i][j][r] = 0.f;

    /* prologue: stage 0 */
#pragma unroll
    for (int i = 0; i < 4; i++) {
        cp16(dstA + i * 16, Ag + i * 4);
        cp16(dstB + i * 16, Bg + i * 4);
    }
    asm volatile("cp.async.commit_group;" ::: "memory");

    const int rb = wm * 64;             /* warp row base in tile */
    const int cb = wn * 32;             /* warp col base in tile */

    for (int c = 0; c < NCH; c++) {
        const int cur = c & 1;
        if (c + 1 < NCH) {
            const int nxt = (c + 1) & 1;
            const int k0 = (c + 1) * BKK;
#pragma unroll
            for (int i = 0; i < 4; i++) {
                cp16(dstA + (uint32_t)(nxt * STG_F * 4) + i * 16, Ag + k0 + i * 4);
                cp16(dstB + (uint32_t)(nxt * STG_F * 4) + i * 16, Bg + k0 + i * 4);
            }
            asm volatile("cp.async.commit_group;" ::: "memory");
            asm volatile("cp.async.wait_group 1;" ::: "memory");
        } else {
            asm volatile("cp.async.wait_group 0;" ::: "memory");
        }
        __syncthreads();

        const float* As = sm  + cur * STG_F;
        const float* Bs = Bsm + cur * STG_F;
#pragma unroll
        for (int ks = 0; ks < 4; ks++) {
            const int k = ks * 8;
            uint32_t af[4][4], bf[4][2];
#pragma unroll
            for (int mf = 0; mf < 4; mf++) {
                const float* ap = As + (rb + mf * 16 + g) * ASTR + k + tig;
                af[mf][0] = f2tf32(ap[0]);
                af[mf][1] = f2tf32(ap[8 * ASTR]);
                af[mf][2] = f2tf32(ap[4]);
                af[mf][3] = f2tf32(ap[8 * ASTR + 4]);
            }
#pragma unroll
            for (int nf = 0; nf < 4; nf++) {
                const float* bp = Bs + (cb + nf * 8 + g) * ASTR + k + tig;
                bf[nf][0] = f2tf32(bp[0]);
                bf[nf][1] = f2tf32(bp[4]);
            }
#pragma unroll
            for (int mf = 0; mf < 4; mf++)
#pragma unroll
                for (int nf = 0; nf < 4; nf++)
                    mma_tf32(acc[mf][nf], af[mf], bf[nf]);
        }
        __syncthreads();
    }

    /* epilogue: c0/c1 -> (row, col..col+1), c2/c3 -> (row+8, ...) */
    const int row0 = blockIdx.y * 128 + rb + g;
    const int col0 = blockIdx.x * 128 + cb + tig * 2;
#pragma unroll
    for (int nf = 0; nf < 4; nf++) {
        const int col = col0 + nf * 8;
        const float b0 = bias[col], b1 = bias[col + 1];
#pragma unroll
        for (int mf = 0; mf < 4; mf++) {
            const int r = row0 + mf * 16;
            float2 v0 = make_float2(acc[mf][nf][0] + b0, acc[mf][nf][1] + b1);
            float2 v1 = make_float2(acc[mf][nf][2] + b0, acc[mf][nf][3] + b1);
            *(float2*)(C + (size_t)r * N + col)       = v0;
            *(float2*)(C + (size_t)(r + 8) * N + col) = v1;
        }
    }
}

/* ---- weight transpose: D[c][r] = S[r][c] ---- */
__global__ void transpose_kernel(const float* __restrict__ S, float* __restrict__ D,
                                 int R, int Cc)
{
    __shared__ float t[32][33];
    const int bx = blockIdx.x * 32, by = blockIdx.y * 32;
    const int x = threadIdx.x, y = threadIdx.y;   /* 32 x 8 */
#pragma unroll
    for (int j = 0; j < 32; j += 8)
        t[y + j][x] = S[(size_t)(by + y + j) * Cc + bx + x];
    __syncthreads();
#pragma unroll
    for (int j = 0; j < 32; j += 8)
        D[(size_t)(bx + y + j) * R + by + x] = t[x][y + j];
}

/* ---------------- softmaxes & small GEMMs ---------------- */

__global__ void q_softmax_kernel(float* __restrict__ qkv)
{
    const int b       = blockIdx.x / (DIMM / 32);
    const int colbase = (blockIdx.x % (DIMM / 32)) * 32;
    const int c = threadIdx.x & 31;
    const int r = threadIdx.x >> 5;
    const int stride = QKVN;
    float* base = qkv + (size_t)b * SS * stride + colbase + c;

    __shared__ float red[8][32];

    float mx = -INFINITY;
    for (int s = r; s < SS; s += 8)
        mx = fmaxf(mx, base[(size_t)s * stride]);
    red[r][c] = mx;
    __syncthreads();
    if (r == 0) {
        float m = red[0][c];
#pragma unroll
        for (int i = 1; i < 8; i++) m = fmaxf(m, red[i][c]);
        red[0][c] = m;
    }
    __syncthreads();
    mx = red[0][c];
    __syncthreads();

    float sum = 0.f;
    for (int s = r; s < SS; s += 8)
        sum += expf(base[(size_t)s * stride] - mx);
    red[r][c] = sum;
    __syncthreads();
    if (r == 0) {
        float t = 0.f;
#pragma unroll
        for (int i = 0; i < 8; i++) t += red[i][c];
        red[0][c] = t;
    }
    __syncthreads();
    const float inv = SCALE_F / red[0][c];

    for (int s = r; s < SS; s += 8) {
        size_t off = (size_t)s * stride;
        base[off] = expf(base[off] - mx) * inv;
    }
}

__global__ void k_softmax_kernel(float* __restrict__ qkv)
{
    const int row  = blockIdx.x * 8 + (threadIdx.x >> 5);
    const int lane = threadIdx.x & 31;
    float* p = qkv + (size_t)(row / HH) * QKVN + DIMM + (row % HH) * HDD;

    float v0 = p[lane], v1 = p[lane + 32];
    float m = fmaxf(v0, v1);
#pragma unroll
    for (int o = 16; o > 0; o >>= 1)
        m = fmaxf(m, __shfl_xor_sync(0xFFFFFFFFu, m, o));
    float e0 = expf(v0 - m), e1 = expf(v1 - m);
    float s = e0 + e1;
#pragma unroll
    for (int o = 16; o > 0; o >>= 1)
        s += __shfl_xor_sync(0xFFFFFFFFu, s, o);
    float inv = 1.f / s;
    p[lane]      = e0 * inv;
    p[lane + 32] = e1 * inv;
}

__global__ void ktq_kernel(const float* __restrict__ qkv, float* __restrict__ Apart)
{
    const int bh = blockIdx.x / TSPLIT;
    const int ts = blockIdx.x % TSPLIT;
    const int b = bh / HH, h = bh % HH;
    const int TCHUNK = SS / TSPLIT;

    __shared__ __align__(16) float ks[32][64];
    __shared__ __align__(16) float qs[32][64];

    const int tid = threadIdx.x;
    const int tc = tid & 15;
    const int tr = tid >> 4;
    const int lr = tid >> 3;
    const int lc = tid & 7;

    float acc[4][4];
#pragma unroll
    for (int i = 0; i < 4; i++)
#pragma unroll
        for (int j = 0; j < 4; j++) acc[i][j] = 0.f;

    const float* base = qkv + ((size_t)b * SS + (size_t)ts * TCHUNK) * QKVN;

    for (int t0 = 0; t0 < TCHUNK; t0 += 32) {
        const float* qrow = base + (size_t)(t0 + lr) * QKVN + h * HDD;
        const float* krow = qrow + DIMM;
        *(float4*)&qs[lr][lc * 4]      = *(const float4*)(qrow + lc * 4);
        *(float4*)&qs[lr][lc * 4 + 32] = *(const float4*)(qrow + lc * 4 + 32);
        *(float4*)&ks[lr][lc * 4]      = *(const float4*)(krow + lc * 4);
        *(float4*)&ks[lr][lc * 4 + 32] = *(const float4*)(krow + lc * 4 + 32);
        __syncthreads();
#pragma unroll
        for (int kk = 0; kk < 32; kk++) {
            float kr[4], qr[4];
            *(float4*)kr = *(const float4*)&ks[kk][tr * 4];
            *(float4*)qr = *(const float4*)&qs[kk][tc * 4];
#pragma unroll
            for (int i = 0; i < 4; i++)
#pragma unroll
                for (int j = 0; j < 4; j++)
                    acc[i][j] += kr[i] * qr[j];
        }
        __syncthreads();
    }

    float* outp = Apart + ((size_t)ts * BB * HH + bh) * HDD * HDD;
#pragma unroll
    for (int i = 0; i < 4; i++) {
        float4 v = make_float4(acc[i][0], acc[i][1], acc[i][2], acc[i][3]);
        *(float4*)&outp[(tr * 4 + i) * HDD + tc * 4] = v;
    }
}

__global__ void a_reduce_kernel(const float* __restrict__ Apart, float* __restrict__ A)
{
    const int idx = blockIdx.x * 256 + threadIdx.x;
    const size_t stride = (size_t)BB * HH * HDD * HDD;
    float s = 0.f;
#pragma unroll
    for (int p = 0; p < TSPLIT; p++)
        s += Apart[(size_t)p * stride + idx];
    A[idx] = s;
}

__global__ void vA_kernel(const float* __restrict__ qkv, const float* __restrict__ Amat,
                          float* __restrict__ outp)
{
    const int stile = blockIdx.x % (SS / 64);
    const int bh    = blockIdx.x / (SS / 64);
    const int b = bh / HH, h = bh % HH;

    __shared__ __align__(16) float Am[64][64];
    __shared__ __align__(16) float vs[64][68];

    const int tid = threadIdx.x;
    const int tc = tid & 15;
    const int tr = tid >> 4;

    {
        const float4* Ab = (const float4*)(Amat + (size_t)bh * HDD * HDD);
        float4* Ad = (float4*)&Am[0][0];
#pragma unroll
        for (int i = 0; i < 4; i++) Ad[tid + i * 256] = Ab[tid + i * 256];
    }
    {
        const int lr = tid >> 2;
        const int lc = tid & 3;
        const float* vrow = qkv + ((size_t)b * SS + (size_t)stile * 64 + lr) * QKVN
                            + 2 * DIMM + h * HDD;
#pragma unroll
        for (int m = 0; m < 4; m++)
            *(float4*)&vs[lr][(lc + 4 * m) * 4] = *(const float4*)(vrow + (lc + 4 * m) * 4);
    }
    __syncthreads();

    float acc[4][4];
#pragma unroll
    for (int i = 0; i < 4; i++)
#pragma unroll
        for (int j = 0; j < 4; j++) acc[i][j] = 0.f;

#pragma unroll 8
    for (int d = 0; d < 64; d++) {
        float br[4];
        *(float4*)br = *(const float4*)&Am[d][tc * 4];
        float vr[4];
#pragma unroll
        for (int i = 0; i < 4; i++) vr[i] = vs[tr * 4 + i][d];
#pragma unroll
        for (int i = 0; i < 4; i++)
#pragma unroll
            for (int j = 0; j < 4; j++)
                acc[i][j] += vr[i] * br[j];
    }

#pragma unroll
    for (int i = 0; i < 4; i++) {
        size_t row = (size_t)b * SS + (size_t)stile * 64 + tr * 4 + i;
        float4 v = make_float4(acc[i][0], acc[i][1], acc[i][2], acc[i][3]);
        *(float4*)(outp + row * DIMM + h * HDD + tc * 4) = v;
    }
}

/* --------------------------------------------------------------- */
extern "C" void kernel_launch(void* const* d_in, const int* in_sizes, int n_in,
                              void* d_out, int out_size)
{
    (void)in_sizes; (void)n_in; (void)out_size;
    const float* x     = (const float*)d_in[0];
    const float* Wqkv  = (const float*)d_in[1];
    const float* bqkv  = (const float*)d_in[2];
    const float* Wproj = (const float*)d_in[3];
    const float* bproj = (const float*)d_in[4];
    float* out = (float*)d_out;

    float *qkv, *attn, *Apart, *Amat, *WqkvT, *WprojT;
    cudaGetSymbolAddress((void**)&qkv,    g_qkv);
    cudaGetSymbolAddress((void**)&attn,   g_attn);
    cudaGetSymbolAddress((void**)&Apart,  g_Apart);
    cudaGetSymbolAddress((void**)&Amat,   g_A);
    cudaGetSymbolAddress((void**)&WqkvT,  g_WqkvT);
    cudaGetSymbolAddress((void**)&WprojT, g_WprojT);

    cudaFuncSetAttribute(gemm_tc, cudaFuncAttributeMaxDynamicSharedMemorySize, SMEM_DYN_G);

    /* 0) transpose weights to [N][K] */
    {
        dim3 blk(32, 8);
        transpose_kernel<<<dim3(QKVN / 32, DIMM / 32), blk>>>(Wqkv, WqkvT, DIMM, QKVN);
        transpose_kernel<<<dim3(DIMM / 32, DIMM / 32), blk>>>(Wproj, WprojT, DIMM, DIMM);
    }
    /* 1) qkv = x @ Wqkv + bqkv  (tf32 mma.sync) */
    gemm_tc<<<dim3(QKVN / 128, BSR / 128), 256, SMEM_DYN_G>>>(x, WqkvT, bqkv, qkv, QKVN);
    /* 2) softmaxes (in place) */
    q_softmax_kernel<<<BB * (DIMM / 32), 256>>>(qkv);
    k_softmax_kernel<<<(BSR * HH) / 8, 256>>>(qkv);
    /* 3) A = K^T Q per (b,h) */
    ktq_kernel<<<BB * HH * TSPLIT, 256>>>(qkv, Apart);
    a_reduce_kernel<<<(BB * HH * HDD * HDD) / 256, 256>>>(Apart, Amat);
    /* 4) attn = V @ A per (b,h) */
    vA_kernel<<<BB * HH * (SS / 64), 256>>>(qkv, Amat, attn);
    /* 5) out = attn @ Wproj + bproj  (tf32 mma.sync) */
    gemm_tc<<<dim3(DIMM / 128, BSR / 128), 256, SMEM_DYN_G>>>(attn, WprojT, bproj, out, DIMM);
}

// round 4
// speedup vs baseline: 1.9171x; 1.0846x over previous
#include <cuda_runtime.h>
#include <cstdint>
#include <math.h>

#define BB   8
#define SS   4096
#define DIMM 1024
#define HH   16
#define HDD  64
#define BSR  (BB * SS)          /* 32768 rows */
#define QKVN (3 * DIMM)         /* 3072 */
#define TSPLIT 32
#define SCALE_F 0.125f          /* 64^-0.5 */
#define KDIM 1024               /* K of both big GEMMs */

/* -------- scratch (device globals: allocation-free rule) -------- */
__device__ float g_qkv[(size_t)BSR * QKVN];                       /* 402 MB */
__device__ float g_attn[(size_t)BSR * DIMM];                      /* 134 MB */
__device__ float g_Apart[(size_t)TSPLIT * BB * HH * HDD * HDD];   /* 67 MB  */
__device__ float g_A[(size_t)BB * HH * HDD * HDD];                /* 2 MB   */
__device__ float g_WqkvT[(size_t)QKVN * DIMM];                    /* 12 MB  */
__device__ float g_WprojT[(size_t)DIMM * DIMM];                   /* 4 MB   */
__device__ float g_xr[(size_t)BSR * DIMM];                        /* 134 MB */

__device__ __forceinline__ uint32_t f2tf32(float x) {
    uint32_t r;
    asm("cvt.rna.tf32.f32 %0, %1;" : "=r"(r) : "f"(x));
    return r;
}
__device__ __forceinline__ float roundtf(float x) {
    return __uint_as_float(f2tf32(x));
}

/* ================= tf32 mma.sync GEMM =================
 * Inputs MUST be pre-rounded to the tf32 grid (mantissa rna-rounded);
 * the hot loop feeds raw fp32 bits to HMMA with no cvt. */

#define BKK   32
#define ASTR  36                      /* padded row stride in floats */
#define STG_F (128 * ASTR)            /* floats per stage per matrix */
#define SMEM_DYN_G (4 * STG_F * 4)    /* 2 stages x (A+B) = 73728 B */
#define NCH   (KDIM / BKK)            /* 32 */

__device__ __forceinline__ uint32_t smem_u32(const void* p) {
    uint32_t a;
    asm("{ .reg .u64 t; cvta.to.shared.u64 t, %1; cvt.u32.u64 %0, t; }"
        : "=r"(a) : "l"(p));
    return a;
}
__device__ __forceinline__ void cp16(uint32_t dst, const void* src) {
    asm volatile("cp.async.cg.shared.global [%0], [%1], 16;"
                 :: "r"(dst), "l"(src) : "memory");
}
__device__ __forceinline__ void mma_tf32(float* c, const uint32_t* a, const uint32_t* b) {
    asm volatile("mma.sync.aligned.m16n8k8.row.col.f32.tf32.tf32.f32 "
                 "{%0,%1,%2,%3}, {%4,%5,%6,%7}, {%8,%9}, {%0,%1,%2,%3};"
                 : "+f"(c[0]), "+f"(c[1]), "+f"(c[2]), "+f"(c[3])
                 : "r"(a[0]), "r"(a[1]), "r"(a[2]), "r"(a[3]),
                   "r"(b[0]), "r"(b[1]));
}

__global__ void __launch_bounds__(256, 2)
gemm_tc(const float* __restrict__ A, const float* __restrict__ BT,
        const float* __restrict__ bias, float* __restrict__ C, int N)
{
    extern __shared__ __align__(16) float sm[];
    float* Bsm = sm + 2 * STG_F;
    const uint32_t uA = smem_u32(sm);
    const uint32_t uB = uA + 2 * STG_F * 4;

    const int tid  = threadIdx.x;
    const int lane = tid & 31;
    const int warp = tid >> 5;
    const int wm   = warp & 1;          /* warp row: 0..1 */
    const int wn   = warp >> 1;         /* warp col: 0..3 */
    const int g    = lane >> 2;         /* group 0..7 */
    const int tig  = lane & 3;          /* 0..3 */

    const int arow = tid >> 1;          /* 0..127 */
    const int seg  = (tid & 1) * 16;
    const float* Ag = A  + (size_t)(blockIdx.y * 128 + arow) * KDIM + seg;
    const float* Bg = BT + (size_t)(blockIdx.x * 128 + arow) * KDIM + seg;
    const uint32_t dstA = uA + (uint32_t)(arow * ASTR + seg) * 4;
    const uint32_t dstB = uB + (uint32_t)(arow * ASTR + seg) * 4;

    float acc[4][4][4];
#pragma unroll
    for (int i = 0; i < 4; i++)
#pragma unroll
        for (int j = 0; j < 4; j++)
#pragma unroll
            for (int r = 0; r < 4; r++) acc[i][j][r] = 0.f;

#pragma unroll
    for (int i = 0; i < 4; i++) {
        cp16(dstA + i * 16, Ag + i * 4);
        cp16(dstB + i * 16, Bg + i * 4);
    }
    asm volatile("cp.async.commit_group;" ::: "memory");

    const int rb = wm * 64;
    const int cb = wn * 32;

    for (int c = 0; c < NCH; c++) {
        const int cur = c & 1;
        if (c + 1 < NCH) {
            const int nxt = (c + 1) & 1;
            const int k0 = (c + 1) * BKK;
#pragma unroll
            for (int i = 0; i < 4; i++) {
                cp16(dstA + (uint32_t)(nxt * STG_F * 4) + i * 16, Ag + k0 + i * 4);
                cp16(dstB + (uint32_t)(nxt * STG_F * 4) + i * 16, Bg + k0 + i * 4);
            }
            asm volatile("cp.async.commit_group;" ::: "memory");
            asm volatile("cp.async.wait_group 1;" ::: "memory");
        } else {
            asm volatile("cp.async.wait_group 0;" ::: "memory");
        }
        __syncthreads();

        const uint32_t* As = (const uint32_t*)(sm  + cur * STG_F);
        const uint32_t* Bs = (const uint32_t*)(Bsm + cur * STG_F);
#pragma unroll
        for (int ks = 0; ks < 4; ks++) {
            const int k = ks * 8;
            uint32_t af[4][4], bf[4][2];
#pragma unroll
            for (int mf = 0; mf < 4; mf++) {
                const uint32_t* ap = As + (rb + mf * 16 + g) * ASTR + k + tig;
                af[mf][0] = ap[0];
                af[mf][1] = ap[8 * ASTR];
                af[mf][2] = ap[4];
                af[mf][3] = ap[8 * ASTR + 4];
            }
#pragma unroll
            for (int nf = 0; nf < 4; nf++) {
                const uint32_t* bp = Bs + (cb + nf * 8 + g) * ASTR + k + tig;
                bf[nf][0] = bp[0];
                bf[nf][1] = bp[4];
            }
#pragma unroll
            for (int mf = 0; mf < 4; mf++)
#pragma unroll
                for (int nf = 0; nf < 4; nf++)
                    mma_tf32(acc[mf][nf], af[mf], bf[nf]);
        }
        __syncthreads();
    }

    const int row0 = blockIdx.y * 128 + rb + g;
    const int col0 = blockIdx.x * 128 + cb + tig * 2;
#pragma unroll
    for (int nf = 0; nf < 4; nf++) {
        const int col = col0 + nf * 8;
        const float b0 = bias[col], b1 = bias[col + 1];
#pragma unroll
        for (int mf = 0; mf < 4; mf++) {
            const int r = row0 + mf * 16;
            float2 v0 = make_float2(acc[mf][nf][0] + b0, acc[mf][nf][1] + b1);
            float2 v1 = make_float2(acc[mf][nf][2] + b0, acc[mf][nf][3] + b1);
            *(float2*)(C + (size_t)r * N + col)       = v0;
            *(float2*)(C + (size_t)(r + 8) * N + col) = v1;
        }
    }
}

/* ---- weight transpose + tf32 pre-round: D[c][r] = round(S[r][c]) ---- */
__global__ void transpose_kernel(const float* __restrict__ S, float* __restrict__ D,
                                 int R, int Cc)
{
    __shared__ float t[32][33];
    const int bx = blockIdx.x * 32, by = blockIdx.y * 32;
    const int x = threadIdx.x, y = threadIdx.y;   /* 32 x 8 */
#pragma unroll
    for (int j = 0; j < 32; j += 8)
        t[y + j][x] = S[(size_t)(by + y + j) * Cc + bx + x];
    __syncthreads();
#pragma unroll
    for (int j = 0; j < 32; j += 8)
        D[(size_t)(bx + y + j) * R + by + x] = roundtf(t[x][y + j]);
}

/* ---- x -> tf32-rounded copy ---- */
__global__ void round_copy_kernel(const float* __restrict__ S, float* __restrict__ D)
{
    const size_t i = ((size_t)blockIdx.x * 256 + threadIdx.x) * 4;
    float4 v = *(const float4*)(S + i);
    v.x = roundtf(v.x); v.y = roundtf(v.y);
    v.z = roundtf(v.z); v.w = roundtf(v.w);
    *(float4*)(D + i) = v;
}

/* ---------------- softmaxes & small GEMMs ---------------- */

/* grid BB*(DIMM/32), block 1024 = 32 cols x 32 row-lanes */
__global__ void q_softmax_kernel(float* __restrict__ qkv)
{
    const int b       = blockIdx.x / (DIMM / 32);
    const int colbase = (blockIdx.x % (DIMM / 32)) * 32;
    const int c = threadIdx.x & 31;
    const int r = threadIdx.x >> 5;   /* 0..31 */
    const int stride = QKVN;
    float* base = qkv + (size_t)b * SS * stride + colbase + c;

    __shared__ float red[32][33];

    float mx = -INFINITY;
    for (int s = r; s < SS; s += 32)
        mx = fmaxf(mx, base[(size_t)s * stride]);
    red[r][c] = mx;
    __syncthreads();
    if (r == 0) {
        float m = red[0][c];
#pragma unroll
        for (int i = 1; i < 32; i++) m = fmaxf(m, red[i][c]);
        red[0][c] = m;
    }
    __syncthreads();
    mx = red[0][c];
    __syncthreads();

    float sum = 0.f;
    for (int s = r; s < SS; s += 32)
        sum += __expf(base[(size_t)s * stride] - mx);
    red[r][c] = sum;
    __syncthreads();
    if (r == 0) {
        float t = 0.f;
#pragma unroll
        for (int i = 0; i < 32; i++) t += red[i][c];
        red[0][c] = t;
    }
    __syncthreads();
    const float inv = SCALE_F / red[0][c];

    for (int s = r; s < SS; s += 32) {
        size_t off = (size_t)s * stride;
        base[off] = __expf(base[off] - mx) * inv;
    }
}

__global__ void k_softmax_kernel(float* __restrict__ qkv)
{
    const int row  = blockIdx.x * 8 + (threadIdx.x >> 5);
    const int lane = threadIdx.x & 31;
    float* p = qkv + (size_t)(row / HH) * QKVN + DIMM + (row % HH) * HDD;

    float v0 = p[lane], v1 = p[lane + 32];
    float m = fmaxf(v0, v1);
#pragma unroll
    for (int o = 16; o > 0; o >>= 1)
        m = fmaxf(m, __shfl_xor_sync(0xFFFFFFFFu, m, o));
    float e0 = __expf(v0 - m), e1 = __expf(v1 - m);
    float s = e0 + e1;
#pragma unroll
    for (int o = 16; o > 0; o >>= 1)
        s += __shfl_xor_sync(0xFFFFFFFFu, s, o);
    float inv = 1.f / s;
    p[lane]      = e0 * inv;
    p[lane + 32] = e1 * inv;
}

__global__ void ktq_kernel(const float* __restrict__ qkv, float* __restrict__ Apart)
{
    const int bh = blockIdx.x / TSPLIT;
    const int ts = blockIdx.x % TSPLIT;
    const int b = bh / HH, h = bh % HH;
    const int TCHUNK = SS / TSPLIT;

    __shared__ __align__(16) float ks[32][64];
    __shared__ __align__(16) float qs[32][64];

    const int tid = threadIdx.x;
    const int tc = tid & 15;
    const int tr = tid >> 4;
    const int lr = tid >> 3;
    const int lc = tid & 7;

    float acc[4][4];
#pragma unroll
    for (int i = 0; i < 4; i++)
#pragma unroll
        for (int j = 0; j < 4; j++) acc[i][j] = 0.f;

    const float* base = qkv + ((size_t)b * SS + (size_t)ts * TCHUNK) * QKVN;

    for (int t0 = 0; t0 < TCHUNK; t0 += 32) {
        const float* qrow = base + (size_t)(t0 + lr) * QKVN + h * HDD;
        const float* krow = qrow + DIMM;
        *(float4*)&qs[lr][lc * 4]      = *(const float4*)(qrow + lc * 4);
        *(float4*)&qs[lr][lc * 4 + 32] = *(const float4*)(qrow + lc * 4 + 32);
        *(float4*)&ks[lr][lc * 4]      = *(const float4*)(krow + lc * 4);
        *(float4*)&ks[lr][lc * 4 + 32] = *(const float4*)(krow + lc * 4 + 32);
        __syncthreads();
#pragma unroll
        for (int kk = 0; kk < 32; kk++) {
            float kr[4], qr[4];
            *(float4*)kr = *(const float4*)&ks[kk][tr * 4];
            *(float4*)qr = *(const float4*)&qs[kk][tc * 4];
#pragma unroll
            for (int i = 0; i < 4; i++)
#pragma unroll
                for (int j = 0; j < 4; j++)
                    acc[i][j] += kr[i] * qr[j];
        }
        __syncthreads();
    }

    float* outp = Apart + ((size_t)ts * BB * HH + bh) * HDD * HDD;
#pragma unroll
    for (int i = 0; i < 4; i++) {
        float4 v = make_float4(acc[i][0], acc[i][1], acc[i][2], acc[i][3]);
        *(float4*)&outp[(tr * 4 + i) * HDD + tc * 4] = v;
    }
}

__global__ void a_reduce_kernel(const float* __restrict__ Apart, float* __restrict__ A)
{
    const int idx = blockIdx.x * 256 + threadIdx.x;
    const size_t stride = (size_t)BB * HH * HDD * HDD;
    float s = 0.f;
#pragma unroll
    for (int p = 0; p < TSPLIT; p++)
        s += Apart[(size_t)p * stride + idx];
    A[idx] = s;
}

/* vA: writes attn PRE-ROUNDED to tf32 grid (attn is only GEMM2 input) */
__global__ void vA_kernel(const float* __restrict__ qkv, const float* __restrict__ Amat,
                          float* __restrict__ outp)
{
    const int stile = blockIdx.x % (SS / 64);
    const int bh    = blockIdx.x / (SS / 64);
    const int b = bh / HH, h = bh % HH;

    __shared__ __align__(16) float Am[64][64];
    __shared__ __align__(16) float vs[64][68];

    const int tid = threadIdx.x;
    const int tc = tid & 15;
    const int tr = tid >> 4;

    {
        const float4* Ab = (const float4*)(Amat + (size_t)bh * HDD * HDD);
        float4* Ad = (float4*)&Am[0][0];
#pragma unroll
        for (int i = 0; i < 4; i++) Ad[tid + i * 256] = Ab[tid + i * 256];
    }
    {
        const int lr = tid >> 2;
        const int lc = tid & 3;
        const float* vrow = qkv + ((size_t)b * SS + (size_t)stile * 64 + lr) * QKVN
                            + 2 * DIMM + h * HDD;
#pragma unroll
        for (int m = 0; m < 4; m++)
            *(float4*)&vs[lr][(lc + 4 * m) * 4] = *(const float4*)(vrow + (lc + 4 * m) * 4);
    }
    __syncthreads();

    float acc[4][4];
#pragma unroll
    for (int i = 0; i < 4; i++)
#pragma unroll
        for (int j = 0; j < 4; j++) acc[i][j] = 0.f;

#pragma unroll 8
    for (int d = 0; d < 64; d++) {
        float br[4];
        *(float4*)br = *(const float4*)&Am[d][tc * 4];
        float vr[4];
#pragma unroll
        for (int i = 0; i < 4; i++) vr[i] = vs[tr * 4 + i][d];
#pragma unroll
        for (int i = 0; i < 4; i++)
#pragma unroll
            for (int j = 0; j < 4; j++)
                acc[i][j] += vr[i] * br[j];
    }

#pragma unroll
    for (int i = 0; i < 4; i++) {
        size_t row = (size_t)b * SS + (size_t)stile * 64 + tr * 4 + i;
        float4 v = make_float4(roundtf(acc[i][0]), roundtf(acc[i][1]),
                               roundtf(acc[i][2]), roundtf(acc[i][3]));
        *(float4*)(outp + row * DIMM + h * HDD + tc * 4) = v;
    }
}

/* --------------------------------------------------------------- */
extern "C" void kernel_launch(void* const* d_in, const int* in_sizes, int n_in,
                              void* d_out, int out_size)
{
    (void)in_sizes; (void)n_in; (void)out_size;
    const float* x     = (const float*)d_in[0];
    const float* Wqkv  = (const float*)d_in[1];
    const float* bqkv  = (const float*)d_in[2];
    const float* Wproj = (const float*)d_in[3];
    const float* bproj = (const float*)d_in[4];
    float* out = (float*)d_out;

    float *qkv, *attn, *Apart, *Amat, *WqkvT, *WprojT, *xr;
    cudaGetSymbolAddress((void**)&qkv,    g_qkv);
    cudaGetSymbolAddress((void**)&attn,   g_attn);
    cudaGetSymbolAddress((void**)&Apart,  g_Apart);
    cudaGetSymbolAddress((void**)&Amat,   g_A);
    cudaGetSymbolAddress((void**)&WqkvT,  g_WqkvT);
    cudaGetSymbolAddress((void**)&WprojT, g_WprojT);
    cudaGetSymbolAddress((void**)&xr,     g_xr);

    cudaFuncSetAttribute(gemm_tc, cudaFuncAttributeMaxDynamicSharedMemorySize, SMEM_DYN_G);

    /* 0) pre-round inputs to tf32 grid */
    {
        dim3 blk(32, 8);
        transpose_kernel<<<dim3(QKVN / 32, DIMM / 32), blk>>>(Wqkv, WqkvT, DIMM, QKVN);
        transpose_kernel<<<dim3(DIMM / 32, DIMM / 32), blk>>>(Wproj, WprojT, DIMM, DIMM);
        round_copy_kernel<<<(size_t)BSR * DIMM / (256 * 4), 256>>>(x, xr);
    }
    /* 1) qkv = x @ Wqkv + bqkv  (tf32 mma.sync, no cvt in loop) */
    gemm_tc<<<dim3(QKVN / 128, BSR / 128), 256, SMEM_DYN_G>>>(xr, WqkvT, bqkv, qkv, QKVN);
    /* 2) softmaxes (in place) */
    q_softmax_kernel<<<BB * (DIMM / 32), 1024>>>(qkv);
    k_softmax_kernel<<<(BSR * HH) / 8, 256>>>(qkv);
    /* 3) A = K^T Q per (b,h) */
    ktq_kernel<<<BB * HH * TSPLIT, 256>>>(qkv, Apart);
    a_reduce_kernel<<<(BB * HH * HDD * HDD) / 256, 256>>>(Apart, Amat);
    /* 4) attn = V @ A per (b,h), attn pre-rounded */
    vA_kernel<<<BB * HH * (SS / 64), 256>>>(qkv, Amat, attn);
    /* 5) out = attn @ Wproj + bproj  (tf32 mma.sync) */
    gemm_tc<<<dim3(DIMM / 128, BSR / 128), 256, SMEM_DYN_G>>>(attn, WprojT, bproj, out, DIMM);
}